// round 11
// baseline (speedup 1.0000x reference)
#include <cuda_runtime.h>
#include <cuda_bf16.h>
#include <cstdint>

// ---------------------------------------------------------------------------
// Problem constants
// ---------------------------------------------------------------------------
#define NP      63                 // patches per dim
#define NPATCH  3969               // 63*63
#define BL      15876              // 4 * 3969
#define MPAD    16000              // 125 * 128
#define IND     4096
#define HIDD    256

// ---------------------------------------------------------------------------
// Scratch
// ---------------------------------------------------------------------------
__device__ __nv_bfloat16 g_Xb[(size_t)4 * 64 * 256 * 256];  // x in bf16
__device__ __nv_bfloat16 g_H[(size_t)MPAD * HIDD];          // hidden (m-major)
__device__ __nv_bfloat16 g_Y2[(size_t)IND * MPAD];          // Y transposed [n][m]
__device__ __nv_bfloat16 g_W1[(size_t)HIDD * IND];
__device__ __nv_bfloat16 g_W2[(size_t)IND * HIDD];

// ---------------------------------------------------------------------------
// PTX helpers
// ---------------------------------------------------------------------------
__device__ __forceinline__ void cp_async16(uint32_t s, const void* g) {
    asm volatile("cp.async.cg.shared.global [%0], [%1], 16;\n" ::"r"(s), "l"(g));
}
__device__ __forceinline__ void cp_async8z(uint32_t s, const void* g, uint32_t sz) {
    asm volatile("cp.async.ca.shared.global [%0], [%1], 8, %2;\n"
                 ::"r"(s), "l"(g), "r"(sz));
}
__device__ __forceinline__ void cp_commit() {
    asm volatile("cp.async.commit_group;\n");
}
template <int N>
__device__ __forceinline__ void cp_wait() {
    asm volatile("cp.async.wait_group %0;\n" ::"n"(N));
}
__device__ __forceinline__ void ldmx4(uint32_t& r0, uint32_t& r1, uint32_t& r2,
                                      uint32_t& r3, uint32_t addr) {
    asm volatile("ldmatrix.sync.aligned.m8n8.x4.shared.b16 {%0,%1,%2,%3}, [%4];\n"
                 : "=r"(r0), "=r"(r1), "=r"(r2), "=r"(r3)
                 : "r"(addr));
}
__device__ __forceinline__ void mma16816(float c[4], const uint32_t a[4],
                                         const uint32_t b[2]) {
    asm volatile(
        "mma.sync.aligned.m16n8k16.row.col.f32.bf16.bf16.f32 "
        "{%0,%1,%2,%3}, {%4,%5,%6,%7}, {%8,%9}, {%0,%1,%2,%3};\n"
        : "+f"(c[0]), "+f"(c[1]), "+f"(c[2]), "+f"(c[3])
        : "r"(a[0]), "r"(a[1]), "r"(a[2]), "r"(a[3]), "r"(b[0]), "r"(b[1]));
}

// Swizzled byte offset for an Rx32 bf16 tile stored as R/2 phys rows of 128B.
// Conflict-free for cp.async stores and ldmatrix reads (verified R2/R4/R5).
__device__ __forceinline__ uint32_t sw_off(int r, int kc) {
    int pr = r >> 1;
    int pc = (((r & 1) << 2) | kc) ^ (pr & 7);
    return (uint32_t)((pr << 7) + (pc << 4));
}

__device__ __forceinline__ float gelu_exact(float v) {
    return 0.5f * v * (1.0f + erff(v * 0.70710678118654752f));
}

// ---------------------------------------------------------------------------
// Kernel 1a: convert weights to bf16 (both exactly 1048576 elems)
// ---------------------------------------------------------------------------
__global__ void convert_weights(const float* __restrict__ W1,
                                const float* __restrict__ W2) {
    int i = (blockIdx.x * 256 + threadIdx.x) * 4;
    float4 a = *(const float4*)(W1 + i);
    float4 b = *(const float4*)(W2 + i);
    union { uint2 u; __nv_bfloat162 h[2]; } pa, pb;
    pa.h[0] = __floats2bfloat162_rn(a.x, a.y);
    pa.h[1] = __floats2bfloat162_rn(a.z, a.w);
    pb.h[0] = __floats2bfloat162_rn(b.x, b.y);
    pb.h[1] = __floats2bfloat162_rn(b.z, b.w);
    *(uint2*)(g_W1 + i) = pa.u;
    *(uint2*)(g_W2 + i) = pb.u;
}

// ---------------------------------------------------------------------------
// Kernel 1b: convert x to bf16 (16,777,216 elems)
// ---------------------------------------------------------------------------
__global__ void convert_x(const float* __restrict__ x) {
    int i = (blockIdx.x * 256 + threadIdx.x) * 4;
    float4 f = *(const float4*)(x + i);
    union { uint2 u; __nv_bfloat162 h[2]; } v;
    v.h[0] = __floats2bfloat162_rn(f.x, f.y);
    v.h[1] = __floats2bfloat162_rn(f.z, f.w);
    *(uint2*)(g_Xb + i) = v.u;
}

// ---------------------------------------------------------------------------
// Kernel 2: GEMM1 fused with patchify (R5 config).  H = GELU(P @ W1^T + b1)
// CTA tile 128x256x32, 512 threads (16 warps 4x4, warp tile 32x64),
// 4-stage cp.async. grid 125. A gathered on the fly from g_Xb.
// ---------------------------------------------------------------------------
__global__ void __launch_bounds__(512, 1)
gemm1_fused(const float* __restrict__ bias, __nv_bfloat16* __restrict__ H) {
    constexpr int ABYTES = 8192;        // 128 x 32 bf16
    constexpr int BBYTES = 16384;       // 256 x 32 bf16
    constexpr int STAGE_BYTES = ABYTES + BBYTES;  // 24 KB x 4 = 96 KB
    extern __shared__ __align__(128) uint8_t smem_raw[];
    const uint32_t smem = (uint32_t)__cvta_generic_to_shared(smem_raw);

    const int tid = threadIdx.x;
    const int lane = tid & 31, warp = tid >> 5;
    const int wm = warp >> 2, wn = warp & 3;
    const int bm = blockIdx.x * 128;
    constexpr int K = 4096, N = 256, KT = 128;

    // per-thread A gather geometry (fixed across stages)
    const int ar = tid >> 2, akc = tid & 3;
    const int m = bm + ar;
    const bool valid = (m < BL);
    int b = m / NPATCH;
    int l = m - b * NPATCH;
    int ih = l / NP;
    int iw = l - ih * NP;
    const __nv_bfloat16* aptr =
        valid ? g_Xb + ((size_t)b << 22) + (ih * 4 + akc) * 256 + iw * 4 : g_Xb;
    const uint32_t asz = valid ? 8u : 0u;
    const uint32_t asw = sw_off(ar, akc);

    float acc[2][8][4];
#pragma unroll
    for (int i = 0; i < 2; i++)
#pragma unroll
        for (int j = 0; j < 8; j++)
#pragma unroll
            for (int k = 0; k < 4; k++) acc[i][j][k] = 0.0f;

    auto load_stage = [&](int kt) {
        uint32_t sA = smem + (kt & 3) * STAGE_BYTES;
        uint32_t sB = sA + ABYTES;
        // A: gather from g_Xb. chunk kt -> c = kt>>1, kh0 = (kt&1)*4
        const __nv_bfloat16* as = aptr + ((kt >> 1) << 16) + ((kt & 1) << 10);
        cp_async8z(sA + asw, as, asz);
        cp_async8z(sA + asw + 8, as + 4, asz);
        // B: W1 rows (K-major, stride 4096)
        const __nv_bfloat16* Bg = g_W1 + kt * 32;
#pragma unroll
        for (int i = 0; i < 2; i++) {
            int q = tid + (i << 9);
            int r = q >> 2, kc = q & 3;
            cp_async16(sB + sw_off(r, kc), Bg + (long)r * K + (kc << 3));
        }
    };

    load_stage(0); cp_commit();
    load_stage(1); cp_commit();
    load_stage(2); cp_commit();

    for (int kt = 0; kt < KT; kt++) {
        if (kt + 2 < KT) cp_wait<2>(); else cp_wait<0>();
        __syncthreads();
        int kn = kt + 3;
        if (kn < KT) load_stage(kn);
        cp_commit();

        uint32_t sA = smem + (kt & 3) * STAGE_BYTES;
        uint32_t sB = sA + ABYTES;
#pragma unroll
        for (int kk = 0; kk < 2; kk++) {
            uint32_t a[2][4];
#pragma unroll
            for (int mi = 0; mi < 2; mi++) {
                int r = wm * 32 + mi * 16 + (lane & 15);
                int kc = (kk << 1) | (lane >> 4);
                ldmx4(a[mi][0], a[mi][1], a[mi][2], a[mi][3], sA + sw_off(r, kc));
            }
            uint32_t bfr[8][2];
#pragma unroll
            for (int nj = 0; nj < 4; nj++) {
                int r = wn * 64 + nj * 16 + (lane & 7) + ((lane & 16) >> 1);
                int kc = (kk << 1) | ((lane >> 3) & 1);
                uint32_t t0, t1, t2, t3;
                ldmx4(t0, t1, t2, t3, sB + sw_off(r, kc));
                bfr[nj * 2][0] = t0; bfr[nj * 2][1] = t1;
                bfr[nj * 2 + 1][0] = t2; bfr[nj * 2 + 1][1] = t3;
            }
#pragma unroll
            for (int mi = 0; mi < 2; mi++)
#pragma unroll
                for (int ni = 0; ni < 8; ni++) mma16816(acc[mi][ni], a[mi], bfr[ni]);
        }
    }

    const long crow = bm + wm * 32 + (lane >> 2);
#pragma unroll
    for (int mi = 0; mi < 2; mi++) {
#pragma unroll
        for (int ni = 0; ni < 8; ni++) {
            long col = wn * 64 + ni * 8 + ((lane & 3) << 1);
            float b0 = bias[col], b1 = bias[col + 1];
            float v0 = gelu_exact(acc[mi][ni][0] + b0);
            float v1 = gelu_exact(acc[mi][ni][1] + b1);
            float v2 = gelu_exact(acc[mi][ni][2] + b0);
            float v3 = gelu_exact(acc[mi][ni][3] + b1);
            long r0 = crow + mi * 16;
            *(__nv_bfloat162*)(H + r0 * N + col) = __floats2bfloat162_rn(v0, v1);
            *(__nv_bfloat162*)(H + (r0 + 8) * N + col) = __floats2bfloat162_rn(v2, v3);
        }
    }
}

// ---------------------------------------------------------------------------
// Kernel 3: GEMM2 transposed:  Y2[n][m] = (W2 @ H^T)[n][m] + b2[n]
// A = W2 (4096x256 K-major), B = H (16000x256 K-major).
// 128x128x32 tiles, 256 threads, 2 CTAs/SM, 4 stages.
// grid (125, 32): x = m tile, y = n tile. Row-major [n][16000] output is
// contiguous in m -> fully coalesced stores AND coalesced fold reads.
// ---------------------------------------------------------------------------
__global__ void __launch_bounds__(256, 2)
gemm2t(const float* __restrict__ bias, __nv_bfloat16* __restrict__ Y2) {
    constexpr int ABYTES = 8192;
    constexpr int BBYTES = 8192;
    constexpr int STAGE_BYTES = ABYTES + BBYTES;  // 16 KB x 4 = 64 KB
    constexpr int K = 256, KT = 8;
    extern __shared__ __align__(128) uint8_t smem_raw[];
    const uint32_t smem = (uint32_t)__cvta_generic_to_shared(smem_raw);

    const int tid = threadIdx.x;
    const int lane = tid & 31, warp = tid >> 5;
    const int wm = warp >> 1, wn = warp & 1;
    const long bm = (long)blockIdx.y * 128;   // n tile (rows of W2)
    const long bn = (long)blockIdx.x * 128;   // m tile (rows of H)

    float acc[2][8][4];
#pragma unroll
    for (int i = 0; i < 2; i++)
#pragma unroll
        for (int j = 0; j < 8; j++)
#pragma unroll
            for (int k = 0; k < 4; k++) acc[i][j][k] = 0.0f;

    auto load_stage = [&](int kt) {
        const __nv_bfloat16* Ag = g_W2 + bm * K + kt * 32;
        const __nv_bfloat16* Bg = g_H + bn * K + kt * 32;
        uint32_t sA = smem + (kt & 3) * STAGE_BYTES;
        uint32_t sB = sA + ABYTES;
#pragma unroll
        for (int i = 0; i < 2; i++) {
            int q = tid + (i << 8);
            int r = q >> 2, kc = q & 3;
            cp_async16(sA + sw_off(r, kc), Ag + (long)r * K + (kc << 3));
        }
#pragma unroll
        for (int i = 0; i < 2; i++) {
            int q = tid + (i << 8);
            int r = q >> 2, kc = q & 3;
            cp_async16(sB + sw_off(r, kc), Bg + (long)r * K + (kc << 3));
        }
    };

    load_stage(0); cp_commit();
    load_stage(1); cp_commit();
    load_stage(2); cp_commit();

    for (int kt = 0; kt < KT; kt++) {
        if (kt + 2 < KT) cp_wait<2>(); else cp_wait<0>();
        __syncthreads();
        int kn = kt + 3;
        if (kn < KT) load_stage(kn);
        cp_commit();

        uint32_t sA = smem + (kt & 3) * STAGE_BYTES;
        uint32_t sB = sA + ABYTES;
#pragma unroll
        for (int kk = 0; kk < 2; kk++) {
            uint32_t a[2][4];
#pragma unroll
            for (int mi = 0; mi < 2; mi++) {
                int r = wm * 32 + mi * 16 + (lane & 15);
                int kc = (kk << 1) | (lane >> 4);
                ldmx4(a[mi][0], a[mi][1], a[mi][2], a[mi][3], sA + sw_off(r, kc));
            }
            uint32_t bfr[8][2];
#pragma unroll
            for (int nj = 0; nj < 4; nj++) {
                int r = wn * 64 + nj * 16 + (lane & 7) + ((lane & 16) >> 1);
                int kc = (kk << 1) | ((lane >> 3) & 1);
                uint32_t t0, t1, t2, t3;
                ldmx4(t0, t1, t2, t3, sB + sw_off(r, kc));
                bfr[nj * 2][0] = t0; bfr[nj * 2][1] = t1;
                bfr[nj * 2 + 1][0] = t2; bfr[nj * 2 + 1][1] = t3;
            }
#pragma unroll
            for (int mi = 0; mi < 2; mi++)
#pragma unroll
                for (int ni = 0; ni < 8; ni++) mma16816(acc[mi][ni], a[mi], bfr[ni]);
        }
    }

    // epilogue: rows = n (bias by row), cols = m, Y2 stride MPAD
    const long crow = bm + wm * 32 + (lane >> 2);
#pragma unroll
    for (int mi = 0; mi < 2; mi++) {
        long r0 = crow + mi * 16;
        float bz0 = bias[r0], bz1 = bias[r0 + 8];
#pragma unroll
        for (int ni = 0; ni < 8; ni++) {
            long col = bn + wn * 64 + ni * 8 + ((lane & 3) << 1);
            float v0 = acc[mi][ni][0] + bz0;
            float v1 = acc[mi][ni][1] + bz0;
            float v2 = acc[mi][ni][2] + bz1;
            float v3 = acc[mi][ni][3] + bz1;
            *(__nv_bfloat162*)(Y2 + r0 * MPAD + col) = __floats2bfloat162_rn(v0, v1);
            *(__nv_bfloat162*)(Y2 + (r0 + 8) * MPAD + col) =
                __floats2bfloat162_rn(v2, v3);
        }
    }
}

// ---------------------------------------------------------------------------
// Kernel 4: gather-fold + residual on transposed Y2.
// out = x + softplus(alpha_raw) * fold(Y)/norm
// One thread per pixel; block = one (b, c, h) row of 256 pixels.
// Y2 read: [(c*64+kh*8+kw)][b*3969 + ih*63 + iw] -> contiguous in iw/w.
// ---------------------------------------------------------------------------
__global__ void fold_kernel(const float* __restrict__ x,
                            const float* __restrict__ alpha_raw,
                            float* __restrict__ out) {
    const int w = threadIdx.x;
    const int blk = blockIdx.x;            // 65536 = 4*64*256
    const int h = blk & 255;
    const int c = (blk >> 8) & 63;
    const int b = blk >> 14;

    float alpha = log1pf(__expf(alpha_raw[0]));

    int ih_lo = max(0, (h - 4) >> 2);
    int ih_hi = min(62, h >> 2);
    int iw_lo = max(0, (w - 4) >> 2);
    int iw_hi = min(62, w >> 2);
    int cnt = (ih_hi - ih_lo + 1) * (iw_hi - iw_lo + 1);

    const int mB = b * NPATCH;
    float s = 0.f;
    for (int ih = ih_lo; ih <= ih_hi; ih++) {
        int kh = h - 4 * ih;
        const __nv_bfloat16* Yb = g_Y2 + (size_t)(c * 64 + kh * 8) * MPAD;
        int mrow = mB + ih * NP;
        for (int iw = iw_lo; iw <= iw_hi; iw++) {
            int kw = w - 4 * iw;
            s += __bfloat162float(Yb[(size_t)kw * MPAD + mrow + iw]);
        }
    }
    float sc = alpha / (float)cnt;
    size_t xi = (size_t)blk * 256 + w;
    out[xi] = fmaf(s, sc, x[xi]);
}

// ---------------------------------------------------------------------------
// Launch
// ---------------------------------------------------------------------------
extern "C" void kernel_launch(void* const* d_in, const int* in_sizes, int n_in,
                              void* d_out, int out_size) {
    const float* x         = (const float*)d_in[0];
    const float* W1        = (const float*)d_in[1];
    const float* b1        = (const float*)d_in[2];
    const float* W2        = (const float*)d_in[3];
    const float* b2        = (const float*)d_in[4];
    const float* alpha_raw = (const float*)d_in[5];
    float* out             = (float*)d_out;

    void *pH, *pY2;
    cudaGetSymbolAddress(&pH, g_H);
    cudaGetSymbolAddress(&pY2, g_Y2);

    const int SM1 = 4 * 24576;  // 96 KB
    const int SM2 = 4 * 16384;  // 64 KB
    cudaFuncSetAttribute(gemm1_fused,
                         cudaFuncAttributeMaxDynamicSharedMemorySize, SM1);
    cudaFuncSetAttribute(gemm2t,
                         cudaFuncAttributeMaxDynamicSharedMemorySize, SM2);

    convert_weights<<<1024, 256>>>(W1, W2);
    convert_x<<<16384, 256>>>(x);
    // GEMM1 (+patchify): H = GELU(P @ W1^T + b1)   M=16000, N=256, K=4096
    gemm1_fused<<<125, 512, SM1>>>(b1, (__nv_bfloat16*)pH);
    // GEMM2 (transposed): Y2[4096][16000] = W2 @ H^T + b2
    gemm2t<<<dim3(125, 32), 256, SM2>>>(b2, (__nv_bfloat16*)pY2);
    fold_kernel<<<65536, 256>>>(x, alpha_raw, out);
}